// round 3
// baseline (speedup 1.0000x reference)
#include <cuda_runtime.h>

#define N_PTS   131072
#define K_CB    1024
#define NPAIR   512          // K_CB / 2
#define D_DIM   10
#define PROW    24           // floats per code-pair row: 10 f32x2 dims + esq pair + pad
#define THREADS 256
#define NBLOCKS (N_PTS / THREADS)   // 512, PPT = 1

__device__ float        g_partials[NBLOCKS];
__device__ unsigned int g_done = 0;

__device__ __forceinline__ unsigned long long fma2(
    unsigned long long a, unsigned long long b, unsigned long long c) {
    unsigned long long d;
    asm("fma.rn.f32x2 %0, %1, %2, %3;" : "=l"(d) : "l"(a), "l"(b), "l"(c));
    return d;
}
__device__ __forceinline__ unsigned long long dup2(float v) {
    unsigned long long r;
    asm("mov.b64 %0, {%1, %1};" : "=l"(r) : "f"(v));
    return r;
}
__device__ __forceinline__ void unpack2(unsigned long long v, float& lo, float& hi) {
    asm("mov.b64 {%0, %1}, %2;" : "=f"(lo), "=f"(hi) : "l"(v));
}

// Bit-exact distance pair for one code-pair row (identical FMA order to hot loop).
__device__ __forceinline__ void pair_dists(const ulonglong2* q,
                                           const unsigned long long* xd,
                                           float& d0, float& d1) {
    ulonglong2 w0 = q[0], w1 = q[1], w2 = q[2], w3 = q[3], w4 = q[4], w5 = q[5];
    unsigned long long a = w5.x;
    a = fma2(w0.x, xd[0], a);
    a = fma2(w0.y, xd[1], a);
    a = fma2(w1.x, xd[2], a);
    a = fma2(w1.y, xd[3], a);
    a = fma2(w2.x, xd[4], a);
    a = fma2(w2.y, xd[5], a);
    a = fma2(w3.x, xd[6], a);
    a = fma2(w3.y, xd[7], a);
    a = fma2(w4.x, xd[8], a);
    a = fma2(w4.y, xd[9], a);
    unpack2(a, d0, d1);
}

__global__ void __launch_bounds__(THREADS, 4)
vq_kernel(const float* __restrict__ x,      // [N, D]
          const float* __restrict__ E,      // [K, D]
          float* __restrict__ out)          // [N*D] quantized + loss slot
{
    __shared__ float sE[NPAIR * PROW];      // 49152 bytes
    __shared__ float sred[THREADS / 32];
    __shared__ int   s_last;

    const int tid = threadIdx.x;

    // --- codebook -> pair-packed shared: sE[p*24 + 2j + l] = E[(2p+l)*10 + j] ---
    for (int i = tid; i < K_CB * D_DIM; i += THREADS) {
        int k = i / D_DIM;
        int j = i - k * D_DIM;
        sE[(k >> 1) * PROW + 2 * j + (k & 1)] = E[i];
    }
    __syncthreads();
    for (int k = tid; k < K_CB; k += THREADS) {
        int p = k >> 1, l = k & 1;
        float s = 0.f;
        #pragma unroll
        for (int j = 0; j < D_DIM; j++) {
            float v = sE[p * PROW + 2 * j + l];
            s += v * v;
        }
        sE[p * PROW + 20 + l] = s;
        if (l == 0) { sE[p * PROW + 22] = 0.f; sE[p * PROW + 23] = 0.f; }
    }
    __syncthreads();

    // --- this thread's single point ---
    const int n0 = blockIdx.x * THREADS + tid;

    unsigned long long xd[D_DIM];
    {
        const float* xp = x + (size_t)n0 * D_DIM;
        #pragma unroll
        for (int j = 0; j < D_DIM; j++)
            xd[j] = dup2(-2.f * xp[j]);
    }

    // --- argmin scan: 2 codes/iter via f32x2 lanes, deferred lane pick ---
    float best = 3.402823466e+38f;
    int bp = 0;

    const ulonglong2* sp = (const ulonglong2*)sE;   // 6 per pair row

    #pragma unroll 2
    for (int p = 0; p < NPAIR; ++p) {
        ulonglong2 w0 = sp[0], w1 = sp[1], w2 = sp[2];
        ulonglong2 w3 = sp[3], w4 = sp[4], w5 = sp[5];
        sp += 6;

        unsigned long long a = w5.x;                 // (esq0, esq1)
        a = fma2(w0.x, xd[0], a);
        a = fma2(w0.y, xd[1], a);
        a = fma2(w1.x, xd[2], a);
        a = fma2(w1.y, xd[3], a);
        a = fma2(w2.x, xd[4], a);
        a = fma2(w2.y, xd[5], a);
        a = fma2(w3.x, xd[6], a);
        a = fma2(w3.y, xd[7], a);
        a = fma2(w4.x, xd[8], a);
        a = fma2(w4.y, xd[9], a);

        float d0, d1;
        unpack2(a, d0, d1);
        float m = fminf(d0, d1);                    // FMNMX (alu pipe)
        if (m < best) { best = m; bp = p; }         // strict < keeps first min
    }

    // --- resolve winning lane (bit-exact recompute), write output + loss ---
    float part = 0.f;
    {
        float d0, d1;
        pair_dists((const ulonglong2*)(sE + bp * PROW), xd, d0, d1);
        int lane = (d1 < d0) ? 1 : 0;               // tie -> lane 0 (lower k)
        const float* er = sE + bp * PROW;
        const float* xr = x + (size_t)n0 * D_DIM;
        float* o = out + (size_t)n0 * D_DIM;
        #pragma unroll
        for (int j = 0; j < D_DIM; j++) {
            float q = er[2 * j + lane];
            o[j] = q;
            float dd = xr[j] - q;
            part += dd * dd;
        }
    }

    // --- deterministic loss: warp reduce -> CTA reduce -> per-CTA partial ---
    #pragma unroll
    for (int off = 16; off > 0; off >>= 1)
        part += __shfl_down_sync(0xFFFFFFFFu, part, off);
    if ((tid & 31) == 0) sred[tid >> 5] = part;
    __syncthreads();

    if (tid == 0) {
        float s = 0.f;
        #pragma unroll
        for (int w = 0; w < THREADS / 32; w++) s += sred[w];
        g_partials[blockIdx.x] = s;
        __threadfence();
        unsigned int old = atomicAdd(&g_done, 1u);
        s_last = (old == NBLOCKS - 1) ? 1 : 0;
    }
    __syncthreads();

    // --- last CTA finalizes the loss (fixed order -> deterministic) ---
    if (s_last) {
        __shared__ float sfin[THREADS];
        float s = 0.f;
        #pragma unroll
        for (int r = 0; r < NBLOCKS / THREADS; r++)
            s += g_partials[r * THREADS + tid];
        sfin[tid] = s;
        __syncthreads();
        #pragma unroll
        for (int o = THREADS / 2; o > 0; o >>= 1) {
            if (tid < o) sfin[tid] += sfin[tid + o];
            __syncthreads();
        }
        if (tid == 0) {
            out[(size_t)N_PTS * D_DIM] = sfin[0] * (1.0f / ((float)N_PTS * (float)D_DIM));
            g_done = 0;   // reset for next graph replay
        }
    }
}

extern "C" void kernel_launch(void* const* d_in, const int* in_sizes, int n_in,
                              void* d_out, int out_size) {
    const float* x = (const float*)d_in[0];   // encoder_embedding [N, D]
    const float* E = (const float*)d_in[1];   // embedding_weight  [K, D]
    float* out = (float*)d_out;

    vq_kernel<<<NBLOCKS, THREADS>>>(x, E, out);
}

// round 4
// speedup vs baseline: 1.3285x; 1.3285x over previous
#include <cuda_runtime.h>

#define N_PTS   131072
#define K_CB    1024
#define NPAIR   512          // K_CB / 2
#define D_DIM   10
#define PROW    20           // floats per code-pair row: 10 dims x f32x2 (esq separate)
#define THREADS 64
#define PPT     4
#define NBLOCKS (N_PTS / (THREADS * PPT))   // 512

__device__ float        g_partials[NBLOCKS];
__device__ unsigned int g_done = 0;

__device__ __forceinline__ unsigned long long fma2(
    unsigned long long a, unsigned long long b, unsigned long long c) {
    unsigned long long d;
    asm("fma.rn.f32x2 %0, %1, %2, %3;" : "=l"(d) : "l"(a), "l"(b), "l"(c));
    return d;
}
__device__ __forceinline__ unsigned long long dup2(float v) {
    unsigned long long r;
    asm("mov.b64 %0, {%1, %1};" : "=l"(r) : "f"(v));
    return r;
}
__device__ __forceinline__ unsigned long long pk(float lo, float hi) {
    unsigned long long r;
    asm("mov.b64 %0, {%1, %2};" : "=l"(r) : "f"(lo), "f"(hi));
    return r;
}
__device__ __forceinline__ void unpack2(unsigned long long v, float& lo, float& hi) {
    asm("mov.b64 {%0, %1}, %2;" : "=f"(lo), "=f"(hi) : "l"(v));
}

// Bit-exact distance pair for one code-pair row (same FMA order as hot loop).
__device__ __forceinline__ void pair_dists(const float4* w,
                                           unsigned long long esq,
                                           const unsigned long long* xd,
                                           float& d0, float& d1) {
    float4 w0 = w[0], w1 = w[1], w2 = w[2], w3 = w[3], w4 = w[4];
    unsigned long long a = esq;
    a = fma2(pk(w0.x, w0.y), xd[0], a);
    a = fma2(pk(w0.z, w0.w), xd[1], a);
    a = fma2(pk(w1.x, w1.y), xd[2], a);
    a = fma2(pk(w1.z, w1.w), xd[3], a);
    a = fma2(pk(w2.x, w2.y), xd[4], a);
    a = fma2(pk(w2.z, w2.w), xd[5], a);
    a = fma2(pk(w3.x, w3.y), xd[6], a);
    a = fma2(pk(w3.z, w3.w), xd[7], a);
    a = fma2(pk(w4.x, w4.y), xd[8], a);
    a = fma2(pk(w4.z, w4.w), xd[9], a);
    unpack2(a, d0, d1);
}

__global__ void __launch_bounds__(THREADS, 5)
vq_kernel(const float* __restrict__ x,      // [N, D]
          const float* __restrict__ E,      // [K, D]
          float* __restrict__ out)          // [N*D] quantized + loss slot
{
    __shared__ float sE[NPAIR * PROW];      // 40960 B: pair-packed dims
    __shared__ float sEsq[K_CB];            //  4096 B: esq[k]
    __shared__ float sred[THREADS / 32];
    __shared__ int   s_last;

    const int tid = threadIdx.x;

    // --- codebook -> pair-packed shared: sE[p*20 + 2j + l] = E[(2p+l)*10 + j] ---
    for (int i = tid; i < K_CB * D_DIM; i += THREADS) {
        int k = i / D_DIM;
        int j = i - k * D_DIM;
        sE[(k >> 1) * PROW + 2 * j + (k & 1)] = E[i];
    }
    __syncthreads();
    for (int k = tid; k < K_CB; k += THREADS) {
        int p = k >> 1, l = k & 1;
        float s = 0.f;
        #pragma unroll
        for (int j = 0; j < D_DIM; j++) {
            float v = sE[p * PROW + 2 * j + l];
            s += v * v;
        }
        sEsq[k] = s;
    }
    __syncthreads();

    // --- this thread's four points ---
    const int nbase = blockIdx.x * (THREADS * PPT) + tid;

    unsigned long long xd[PPT][D_DIM];
    #pragma unroll
    for (int q = 0; q < PPT; q++) {
        const float* xp = x + (size_t)(nbase + q * THREADS) * D_DIM;
        #pragma unroll
        for (int j = 0; j < D_DIM; j++)
            xd[q][j] = dup2(-2.f * xp[j]);
    }

    // --- argmin scan: 2 pairs (4 codes) per iter, 4 points, deferred lane ---
    float best[PPT];
    int   bp[PPT];
    #pragma unroll
    for (int q = 0; q < PPT; q++) { best[q] = 3.402823466e+38f; bp[q] = 0; }

    const float4* dims = (const float4*)sE;     // 5 float4 per pair row
    const float4* esq4 = (const float4*)sEsq;   // 4 codes (2 pairs) per float4

    for (int t = 0; t < NPAIR / 2; ++t) {
        float4 e4 = esq4[t];
        unsigned long long esqP0 = pk(e4.x, e4.y);
        unsigned long long esqP1 = pk(e4.z, e4.w);

        const float4* wA = dims + (size_t)(2 * t) * 5;
        float4 a0 = wA[0], a1 = wA[1], a2 = wA[2], a3 = wA[3], a4 = wA[4];
        float4 b0 = wA[5], b1 = wA[6], b2 = wA[7], b3 = wA[8], b4 = wA[9];

        unsigned long long pA0 = pk(a0.x, a0.y), pA1 = pk(a0.z, a0.w);
        unsigned long long pA2 = pk(a1.x, a1.y), pA3 = pk(a1.z, a1.w);
        unsigned long long pA4 = pk(a2.x, a2.y), pA5 = pk(a2.z, a2.w);
        unsigned long long pA6 = pk(a3.x, a3.y), pA7 = pk(a3.z, a3.w);
        unsigned long long pA8 = pk(a4.x, a4.y), pA9 = pk(a4.z, a4.w);

        unsigned long long pB0 = pk(b0.x, b0.y), pB1 = pk(b0.z, b0.w);
        unsigned long long pB2 = pk(b1.x, b1.y), pB3 = pk(b1.z, b1.w);
        unsigned long long pB4 = pk(b2.x, b2.y), pB5 = pk(b2.z, b2.w);
        unsigned long long pB6 = pk(b3.x, b3.y), pB7 = pk(b3.z, b3.w);
        unsigned long long pB8 = pk(b4.x, b4.y), pB9 = pk(b4.z, b4.w);

        #pragma unroll
        for (int q = 0; q < PPT; q++) {
            unsigned long long a = esqP0;
            a = fma2(pA0, xd[q][0], a);
            a = fma2(pA1, xd[q][1], a);
            a = fma2(pA2, xd[q][2], a);
            a = fma2(pA3, xd[q][3], a);
            a = fma2(pA4, xd[q][4], a);
            a = fma2(pA5, xd[q][5], a);
            a = fma2(pA6, xd[q][6], a);
            a = fma2(pA7, xd[q][7], a);
            a = fma2(pA8, xd[q][8], a);
            a = fma2(pA9, xd[q][9], a);
            float d0, d1;
            unpack2(a, d0, d1);
            float m = fminf(d0, d1);
            if (m < best[q]) { best[q] = m; bp[q] = 2 * t; }

            unsigned long long b = esqP1;
            b = fma2(pB0, xd[q][0], b);
            b = fma2(pB1, xd[q][1], b);
            b = fma2(pB2, xd[q][2], b);
            b = fma2(pB3, xd[q][3], b);
            b = fma2(pB4, xd[q][4], b);
            b = fma2(pB5, xd[q][5], b);
            b = fma2(pB6, xd[q][6], b);
            b = fma2(pB7, xd[q][7], b);
            b = fma2(pB8, xd[q][8], b);
            b = fma2(pB9, xd[q][9], b);
            unpack2(b, d0, d1);
            m = fminf(d0, d1);
            if (m < best[q]) { best[q] = m; bp[q] = 2 * t + 1; }
        }
    }

    // --- resolve winning lane per point (bit-exact recompute), write out ---
    float part = 0.f;
    #pragma unroll
    for (int q = 0; q < PPT; q++) {
        int p = bp[q];
        unsigned long long esq = pk(sEsq[2 * p], sEsq[2 * p + 1]);
        float d0, d1;
        pair_dists(dims + (size_t)p * 5, esq, xd[q], d0, d1);
        int lane = (d1 < d0) ? 1 : 0;            // tie -> lane 0 (lower k)
        const float* er = sE + p * PROW;
        float* o = out + (size_t)(nbase + q * THREADS) * D_DIM;
        #pragma unroll
        for (int j = 0; j < D_DIM; j++) {
            float qv = er[2 * j + lane];
            o[j] = qv;
            float lo, hi;
            unpack2(xd[q][j], lo, hi);
            float xv = -0.5f * lo;               // exact: (-0.5)*(-2x) = x
            float dd = xv - qv;
            part += dd * dd;
        }
    }

    // --- deterministic loss: warp reduce -> CTA reduce -> per-CTA partial ---
    #pragma unroll
    for (int off = 16; off > 0; off >>= 1)
        part += __shfl_down_sync(0xFFFFFFFFu, part, off);
    if ((tid & 31) == 0) sred[tid >> 5] = part;
    __syncthreads();

    if (tid == 0) {
        float s = sred[0] + sred[1];
        g_partials[blockIdx.x] = s;
        __threadfence();
        unsigned int old = atomicAdd(&g_done, 1u);
        s_last = (old == NBLOCKS - 1) ? 1 : 0;
    }
    __syncthreads();

    // --- last CTA finalizes loss (fixed order -> deterministic) ---
    if (s_last) {
        __shared__ float sfin[THREADS];
        float s = 0.f;
        #pragma unroll
        for (int r = 0; r < NBLOCKS / THREADS; r++)
            s += g_partials[r * THREADS + tid];
        sfin[tid] = s;
        __syncthreads();
        #pragma unroll
        for (int o = THREADS / 2; o > 0; o >>= 1) {
            if (tid < o) sfin[tid] += sfin[tid + o];
            __syncthreads();
        }
        if (tid == 0) {
            out[(size_t)N_PTS * D_DIM] = sfin[0] * (1.0f / ((float)N_PTS * (float)D_DIM));
            g_done = 0;   // reset for next graph replay
        }
    }
}

extern "C" void kernel_launch(void* const* d_in, const int* in_sizes, int n_in,
                              void* d_out, int out_size) {
    const float* x = (const float*)d_in[0];   // encoder_embedding [N, D]
    const float* E = (const float*)d_in[1];   // embedding_weight  [K, D]
    float* out = (float*)d_out;

    vq_kernel<<<NBLOCKS, THREADS>>>(x, E, out);
}

// round 5
// speedup vs baseline: 1.3568x; 1.0213x over previous
#include <cuda_runtime.h>

#define N_PTS   131072
#define K_CB    1024
#define NPAIR   512          // K_CB / 2
#define D_DIM   10
#define PROW    20           // floats per code-pair row: 10 dims x f32x2 (esq separate)
#define THREADS 64
#define PPT     4
#define NBLOCKS (N_PTS / (THREADS * PPT))   // 512

__device__ float        g_partials[NBLOCKS];
__device__ unsigned int g_done = 0;

__device__ __forceinline__ unsigned long long fma2(
    unsigned long long a, unsigned long long b, unsigned long long c) {
    unsigned long long d;
    asm("fma.rn.f32x2 %0, %1, %2, %3;" : "=l"(d) : "l"(a), "l"(b), "l"(c));
    return d;
}
__device__ __forceinline__ unsigned long long dup2(float v) {
    unsigned long long r;
    asm("mov.b64 %0, {%1, %1};" : "=l"(r) : "f"(v));
    return r;
}
__device__ __forceinline__ void unpack2(unsigned long long v, float& lo, float& hi) {
    asm("mov.b64 {%0, %1}, %2;" : "=f"(lo), "=f"(hi) : "l"(v));
}

// Bit-exact distance pair for one code-pair row (same FMA order as hot loop).
__device__ __forceinline__ void pair_dists(const ulonglong2* w,
                                           unsigned long long esq,
                                           const unsigned long long* xd,
                                           float& d0, float& d1) {
    ulonglong2 c0 = w[0], c1 = w[1], c2 = w[2], c3 = w[3], c4 = w[4];
    unsigned long long a = esq;
    a = fma2(c0.x, xd[0], a);
    a = fma2(c0.y, xd[1], a);
    a = fma2(c1.x, xd[2], a);
    a = fma2(c1.y, xd[3], a);
    a = fma2(c2.x, xd[4], a);
    a = fma2(c2.y, xd[5], a);
    a = fma2(c3.x, xd[6], a);
    a = fma2(c3.y, xd[7], a);
    a = fma2(c4.x, xd[8], a);
    a = fma2(c4.y, xd[9], a);
    unpack2(a, d0, d1);
}

__global__ void __launch_bounds__(THREADS, 5)
vq_kernel(const float* __restrict__ x,      // [N, D]
          const float* __restrict__ E,      // [K, D]
          float* __restrict__ out)          // [N*D] quantized + loss slot
{
    __shared__ float sE[NPAIR * PROW];      // 40960 B: pair-packed dims (f32x2 layout)
    __shared__ float sEsq[K_CB];            //  4096 B: (esq0,esq1) pairs, 8B-aligned
    __shared__ float sred[THREADS / 32];
    __shared__ int   s_last;

    const int tid = threadIdx.x;

    // --- codebook -> pair-packed shared: sE[p*20 + 2j + l] = E[(2p+l)*10 + j] ---
    for (int i = tid; i < K_CB * D_DIM; i += THREADS) {
        int k = i / D_DIM;
        int j = i - k * D_DIM;
        sE[(k >> 1) * PROW + 2 * j + (k & 1)] = E[i];
    }
    __syncthreads();
    for (int k = tid; k < K_CB; k += THREADS) {
        int p = k >> 1, l = k & 1;
        float s = 0.f;
        #pragma unroll
        for (int j = 0; j < D_DIM; j++) {
            float v = sE[p * PROW + 2 * j + l];
            s += v * v;
        }
        sEsq[k] = s;    // layout: [esq(2p), esq(2p+1)] adjacent -> one LDS.64
    }
    __syncthreads();

    // --- this thread's four points ---
    const int nbase = blockIdx.x * (THREADS * PPT) + tid;

    unsigned long long xd[PPT][D_DIM];
    #pragma unroll
    for (int q = 0; q < PPT; q++) {
        const float* xp = x + (size_t)(nbase + q * THREADS) * D_DIM;
        #pragma unroll
        for (int j = 0; j < D_DIM; j++)
            xd[q][j] = dup2(-2.f * xp[j]);
    }

    // --- argmin scan: 1 pair (2 codes) x 4 points per iter, prefetched ---
    float best[PPT];
    int   bp[PPT];
    #pragma unroll
    for (int q = 0; q < PPT; q++) { best[q] = 3.402823466e+38f; bp[q] = 0; }

    const ulonglong2* dims = (const ulonglong2*)sE;          // 5 per pair row
    const unsigned long long* esqp = (const unsigned long long*)sEsq;

    // prime the pipeline with pair 0
    ulonglong2 c0 = dims[0], c1 = dims[1], c2 = dims[2], c3 = dims[3], c4 = dims[4];
    unsigned long long esq = esqp[0];

    for (int p = 0; p < NPAIR; ++p) {
        // prefetch next pair while computing current (wraps harmlessly)
        const int pn = (p + 1) & (NPAIR - 1);
        const ulonglong2* wn = dims + (size_t)pn * 5;
        ulonglong2 n0 = wn[0], n1 = wn[1], n2 = wn[2], n3 = wn[3], n4 = wn[4];
        unsigned long long esqn = esqp[pn];

        #pragma unroll
        for (int q = 0; q < PPT; q++) {
            unsigned long long a = esq;
            a = fma2(c0.x, xd[q][0], a);
            a = fma2(c0.y, xd[q][1], a);
            a = fma2(c1.x, xd[q][2], a);
            a = fma2(c1.y, xd[q][3], a);
            a = fma2(c2.x, xd[q][4], a);
            a = fma2(c2.y, xd[q][5], a);
            a = fma2(c3.x, xd[q][6], a);
            a = fma2(c3.y, xd[q][7], a);
            a = fma2(c4.x, xd[q][8], a);
            a = fma2(c4.y, xd[q][9], a);
            float d0, d1;
            unpack2(a, d0, d1);
            float m = fminf(d0, d1);               // FMNMX (alu pipe)
            if (m < best[q]) { best[q] = m; bp[q] = p; }  // strict < = first min
        }

        c0 = n0; c1 = n1; c2 = n2; c3 = n3; c4 = n4; esq = esqn;
    }

    // --- resolve winning lane per point (bit-exact recompute), write out ---
    float part = 0.f;
    #pragma unroll
    for (int q = 0; q < PPT; q++) {
        int p = bp[q];
        float d0, d1;
        pair_dists(dims + (size_t)p * 5, esqp[p], xd[q], d0, d1);
        int lane = (d1 < d0) ? 1 : 0;              // tie -> lane 0 (lower k)
        const float* er = sE + p * PROW;
        float* o = out + (size_t)(nbase + q * THREADS) * D_DIM;
        #pragma unroll
        for (int j = 0; j < D_DIM; j++) {
            float qv = er[2 * j + lane];
            o[j] = qv;
            float lo, hi;
            unpack2(xd[q][j], lo, hi);
            float xv = -0.5f * lo;                 // exact: (-0.5)*(-2x) = x
            float dd = xv - qv;
            part += dd * dd;
        }
    }

    // --- deterministic loss: warp reduce -> CTA reduce -> per-CTA partial ---
    #pragma unroll
    for (int off = 16; off > 0; off >>= 1)
        part += __shfl_down_sync(0xFFFFFFFFu, part, off);
    if ((tid & 31) == 0) sred[tid >> 5] = part;
    __syncthreads();

    if (tid == 0) {
        float s = sred[0] + sred[1];
        g_partials[blockIdx.x] = s;
        __threadfence();
        unsigned int old = atomicAdd(&g_done, 1u);
        s_last = (old == NBLOCKS - 1) ? 1 : 0;
    }
    __syncthreads();

    // --- last CTA finalizes loss (fixed order -> deterministic) ---
    if (s_last) {
        __shared__ float sfin[THREADS];
        float s = 0.f;
        #pragma unroll
        for (int r = 0; r < NBLOCKS / THREADS; r++)
            s += g_partials[r * THREADS + tid];
        sfin[tid] = s;
        __syncthreads();
        #pragma unroll
        for (int o = THREADS / 2; o > 0; o >>= 1) {
            if (tid < o) sfin[tid] += sfin[tid + o];
            __syncthreads();
        }
        if (tid == 0) {
            out[(size_t)N_PTS * D_DIM] = sfin[0] * (1.0f / ((float)N_PTS * (float)D_DIM));
            g_done = 0;   // reset for next graph replay
        }
    }
}

extern "C" void kernel_launch(void* const* d_in, const int* in_sizes, int n_in,
                              void* d_out, int out_size) {
    const float* x = (const float*)d_in[0];   // encoder_embedding [N, D]
    const float* E = (const float*)d_in[1];   // embedding_weight  [K, D]
    float* out = (float*)d_out;

    vq_kernel<<<NBLOCKS, THREADS>>>(x, E, out);
}